// round 16
// baseline (speedup 1.0000x reference)
#include <cuda_runtime.h>
#include <cuda_bf16.h>
#include <cstdint>

// Inverse 2x2 Haar synthesis — closing variant:
// 1 item/thread, 256-thread blocks, compact 2-op addressing,
// plain (evict-normal) loads AND stores — test store cache policy.
// Input  x: [B=8, 4*C=256, H=256, W=256] fp32  (subband-major: k*C + c)
// Output o: [B=8, C=64, 2H=512, 2W=512] fp32
//
// Work item i = b*2^21 + c*32768 + h*128 + j   (float2-granular, j<128)
//   in_base(float2)  = i + 3*(i & ~(2^21-1))
//   out_base(float4) = 2*i - (i & 127)
// Loads:  4 x LDG.64 (fully coalesced), Stores: 2 x STG.128 (fully coalesced)

static constexpr int      IN_K_STRIDE2 = 64 * 256 * 128;      // 2,097,152 float2
static constexpr int      OW4          = 128;                 // float4 per output row
static constexpr unsigned B_MASK       = ~((1u << 21) - 1u);
static constexpr unsigned N_ITEMS      = 16777216u;

__global__ __launch_bounds__(256)
void iwt_kernel(const float2* __restrict__ in, float4* __restrict__ out)
{
    unsigned i = blockIdx.x * blockDim.x + threadIdx.x;   // < 2^24

    unsigned in_base = i + 3u * (i & B_MASK);

    float2 ll = in[in_base + 0 * IN_K_STRIDE2];
    float2 lh = in[in_base + 1 * IN_K_STRIDE2];
    float2 hl = in[in_base + 2 * IN_K_STRIDE2];
    float2 hh = in[in_base + 3 * IN_K_STRIDE2];

    float s1x = ll.x + lh.x, s2x = hl.x + hh.x;
    float d1x = ll.x - lh.x, d2x = hl.x - hh.x;
    float s1y = ll.y + lh.y, s2y = hl.y + hh.y;
    float d1y = ll.y - lh.y, d2y = hl.y - hh.y;

    const float q = 0.25f;

    float4 r0 = make_float4((s1x + s2x) * q, (s1x - s2x) * q,
                            (s1y + s2y) * q, (s1y - s2y) * q);
    float4 r1 = make_float4((d1x + d2x) * q, (d1x - d2x) * q,
                            (d1y + d2y) * q, (d1y - d2y) * q);

    unsigned out_base = 2u * i - (i & (OW4 - 1));
    out[out_base]       = r0;
    out[out_base + OW4] = r1;
}

extern "C" void kernel_launch(void* const* d_in, const int* in_sizes, int n_in,
                              void* d_out, int out_size)
{
    const float2* in  = (const float2*)d_in[0];
    float4*       out = (float4*)d_out;

    const int threads = 256;
    const int blocks  = (int)(N_ITEMS / threads);   // 65536

    iwt_kernel<<<blocks, threads>>>(in, out);
}